// round 12
// baseline (speedup 1.0000x reference)
#include <cuda_runtime.h>
#include <cuda_fp16.h>
#include <mma.h>

using namespace nvcuda;

#define HDIM 7168
#define NEXP 256
#define TOPK 8
#define SCALE_F 2.5f
#define MAX_T 8192
#define TAU_E 1e-5f
#define TAU_G 2e-5f

#define BM 128
#define BN 64
#define BK 64
#define NTHR 256
#define NIT (HDIM / BK)          // 112
#define LDH 72                   // halves; mult of 8 (wmma) + 16B rows (cp.async)
#define MAT_A (128 * LDH * 2)    // 18432 bytes (one A matrix)
#define MAT_Bb (64 * LDH * 2)    // 9216 bytes (one B matrix)
#define STAGE_B (2 * MAT_A + 2 * MAT_Bb)   // 55296
#define GEMM_SMEM (2 * STAGE_B)            // 110592 -> 2 CTAs/SM

// repair mini-GEMM
#define RCAP 2048
#define RTM 16
#define RKS 14
#define RKLEN 512
#define RNCH (RKLEN / 32)
#define RWS_STRIDE 34
#define RWS_BUF (256 * RWS_STRIDE)
#define REP_SMEM ((RTM * RKLEN + 2 * RWS_BUF) * 4)

__device__ __half  g_Whi[NEXP * HDIM];
__device__ __half  g_Wlo[NEXP * HDIM];
__device__ float   g_scores[MAX_T * NEXP];
__device__ int     g_nflag;
__device__ int     g_flags[MAX_T];
__device__ float2  g_rep[RKS][RCAP][NEXP];

typedef unsigned long long ull;

__device__ __forceinline__ ull pack2(float lo, float hi) {
    ull r; asm("mov.b64 %0, {%1, %2};" : "=l"(r) : "f"(lo), "f"(hi)); return r;
}
__device__ __forceinline__ void fma2_acc(ull& acc, ull a, ull b) {
    asm("fma.rn.f32x2 %0, %1, %2, %0;" : "+l"(acc) : "l"(a), "l"(b));
}
__device__ __forceinline__ ull fma2(ull a, ull b, ull c) {
    ull d; asm("fma.rn.f32x2 %0, %1, %2, %3;" : "=l"(d) : "l"(a), "l"(b), "l"(c)); return d;
}
__device__ __forceinline__ ull add2(ull a, ull b) {
    ull d; asm("add.rn.f32x2 %0, %1, %2;" : "=l"(d) : "l"(a), "l"(b)); return d;
}
__device__ __forceinline__ float2 unpk2(ull v) {
    float lo, hi; asm("mov.b64 {%0, %1}, %2;" : "=f"(lo), "=f"(hi) : "l"(v));
    return make_float2(lo, hi);
}
__device__ __forceinline__ unsigned smem_u32(const void* p) {
    unsigned a;
    asm("{ .reg .u64 t; cvta.to.shared.u64 t, %1; cvt.u32.u64 %0, t; }" : "=r"(a) : "l"(p));
    return a;
}
__device__ __forceinline__ void cp_async16(unsigned saddr, const void* gaddr) {
    asm volatile("cp.async.cg.shared.global [%0], [%1], 16;" :: "r"(saddr), "l"(gaddr));
}
#define CP_COMMIT() asm volatile("cp.async.commit_group;" ::: "memory")
#define CP_WAIT0()  asm volatile("cp.async.wait_group 0;" ::: "memory")

// ---------- K1: split W (x256) into fp16 hi/lo; reset flag counter ----------
__global__ void prep_kernel(const float* __restrict__ W) {
    if (blockIdx.x == 0 && threadIdx.x == 0) g_nflag = 0;
    const int total = NEXP * HDIM;
    for (int i = blockIdx.x * blockDim.x + threadIdx.x; i < total;
         i += gridDim.x * blockDim.x) {
        float ws = W[i] * 256.0f;
        __half h = __float2half_rn(ws);
        g_Whi[i] = h;
        g_Wlo[i] = __float2half_rn(ws - __half2float(h));
    }
}

// ---------- K2: wmma fp16 split-2 GEMM + bias + sigmoid (2 CTAs/SM) ----------
__global__ __launch_bounds__(NTHR, 2)
void gemm_kernel(const float* __restrict__ X, const float* __restrict__ bvec, int T)
{
    extern __shared__ __half sh[];
    const int tid = threadIdx.x;
    const int wid = tid >> 5;
    const int n0 = blockIdx.x * BN;
    const int m0 = blockIdx.y * BM;
    const int wm = wid & 3;          // 4 m-warps (32 rows each)
    const int wn = wid >> 2;         // 2 n-warps (32 cols each)
    const unsigned sbase = smem_u32(sh);

    wmma::fragment<wmma::accumulator, 16, 16, 16, float> acc[2][2];
#pragma unroll
    for (int mt = 0; mt < 2; ++mt)
#pragma unroll
        for (int nt = 0; nt < 2; ++nt) wmma::fill_fragment(acc[mt][nt], 0.0f);

    float4 av[8];

    auto avload = [&](int it) {
        const int kc = it * BK;
#pragma unroll
        for (int i = 0; i < 8; ++i) {
            const int idx = tid + NTHR * i;
            const int row = idx >> 4, c4 = idx & 15;
            av[i] = __ldg((const float4*)(X + (size_t)(m0 + row) * HDIM + kc + c4 * 4));
        }
    };
    auto fillA = [&](int stage) {
        __half* Ahi = sh + stage * (STAGE_B / 2);
        __half* Alo = Ahi + MAT_A / 2;
#pragma unroll
        for (int i = 0; i < 8; ++i) {
            const int idx = tid + NTHR * i;
            const int row = idx >> 4, c4 = idx & 15;
            float4 v = av[i];
            __half2 h01 = __floats2half2_rn(v.x, v.y);
            __half2 h23 = __floats2half2_rn(v.z, v.w);
            float2 f01 = __half22float2(h01), f23 = __half22float2(h23);
            __half2 l01 = __floats2half2_rn(v.x - f01.x, v.y - f01.y);
            __half2 l23 = __floats2half2_rn(v.z - f23.x, v.w - f23.y);
            uint2 ph, pl;
            ph.x = reinterpret_cast<unsigned&>(h01); ph.y = reinterpret_cast<unsigned&>(h23);
            pl.x = reinterpret_cast<unsigned&>(l01); pl.y = reinterpret_cast<unsigned&>(l23);
            *(uint2*)(Ahi + row * LDH + c4 * 4) = ph;
            *(uint2*)(Alo + row * LDH + c4 * 4) = pl;
        }
    };
    auto cpB = [&](int it, int stage) {
        const int kc = it * BK;
        const unsigned bhi = sbase + stage * STAGE_B + 2 * MAT_A;
        const unsigned blo = bhi + MAT_Bb;
#pragma unroll
        for (int i = 0; i < 2; ++i) {
            const int idx = tid + NTHR * i;       // 0..511 over 64 rows x 8 chunks
            const int row = idx >> 3, c8 = idx & 7;
            const unsigned soff = (row * LDH + c8 * 8) * 2;
            const size_t goff = (size_t)(n0 + row) * HDIM + kc + c8 * 8;
            cp_async16(bhi + soff, g_Whi + goff);
            cp_async16(blo + soff, g_Wlo + goff);
        }
        CP_COMMIT();
    };

    cpB(0, 0);
    avload(0);
    fillA(0);
    avload(1);
    CP_WAIT0();
    __syncthreads();

    for (int it = 0; it < NIT; ++it) {
        const int buf = it & 1;
        if (it + 1 < NIT) cpB(it + 1, buf ^ 1);

        const __half* Ahi = sh + buf * (STAGE_B / 2);
        const __half* Alo = Ahi + MAT_A / 2;
        const __half* Bhi = Alo + MAT_A / 2;
        const __half* Blo = Bhi + MAT_Bb / 2;
#pragma unroll
        for (int kk = 0; kk < 4; ++kk) {
            wmma::fragment<wmma::matrix_a, 16, 16, 16, __half, wmma::row_major> ah[2], al[2];
#pragma unroll
            for (int mt = 0; mt < 2; ++mt) {
                const int r = wm * 32 + mt * 16;
                wmma::load_matrix_sync(ah[mt], Ahi + r * LDH + kk * 16, LDH);
                wmma::load_matrix_sync(al[mt], Alo + r * LDH + kk * 16, LDH);
            }
#pragma unroll
            for (int nt = 0; nt < 2; ++nt) {
                const int c = wn * 32 + nt * 16;
                wmma::fragment<wmma::matrix_b, 16, 16, 16, __half, wmma::col_major> fbh, fbl;
                wmma::load_matrix_sync(fbh, Bhi + c * LDH + kk * 16, LDH);
                wmma::load_matrix_sync(fbl, Blo + c * LDH + kk * 16, LDH);
#pragma unroll
                for (int mt = 0; mt < 2; ++mt) {
                    wmma::mma_sync(acc[mt][nt], ah[mt], fbh, acc[mt][nt]);
                    wmma::mma_sync(acc[mt][nt], ah[mt], fbl, acc[mt][nt]);
                    wmma::mma_sync(acc[mt][nt], al[mt], fbh, acc[mt][nt]);
                }
            }
        }
        if (it + 1 < NIT) {
            fillA(buf ^ 1);                  // av regs hold it+1
            if (it + 2 < NIT) avload(it + 2);
            CP_WAIT0();
        }
        __syncthreads();
    }

    float* sacc = (float*)sh;                 // 128 x 64 fp32 = 32 KB
#pragma unroll
    for (int mt = 0; mt < 2; ++mt)
#pragma unroll
        for (int nt = 0; nt < 2; ++nt)
            wmma::store_matrix_sync(sacc + (wm * 32 + mt * 16) * BN + wn * 32 + nt * 16,
                                    acc[mt][nt], BN, wmma::mem_row_major);
    __syncthreads();
#pragma unroll
    for (int i = 0; i < 8; ++i) {
        const int idx = tid + NTHR * i;       // 2048 float4 over 128x16
        const int row = idx >> 4, c4 = idx & 15;
        float4 v = *(float4*)(sacc + row * BN + c4 * 4);
        const int n = n0 + c4 * 4;
        float4 o;
        o.x = 1.0f / (1.0f + expf(-(v.x * (1.0f/256.0f) + bvec[n])));
        o.y = 1.0f / (1.0f + expf(-(v.y * (1.0f/256.0f) + bvec[n+1])));
        o.z = 1.0f / (1.0f + expf(-(v.z * (1.0f/256.0f) + bvec[n+2])));
        o.w = 1.0f / (1.0f + expf(-(v.w * (1.0f/256.0f) + bvec[n+3])));
        *(float4*)(g_scores + (size_t)(m0 + row) * NEXP + n) = o;
    }
}

// ---------- warp-collective routing core ----------
__device__ __forceinline__ void route_token(const float* __restrict__ rs,
                                            const float* __restrict__ ebias,
                                            int lane, int t, int T,
                                            float* __restrict__ out, bool check)
{
    const float NEG_INF = -1e30f;
    float sfc[8];
#pragma unroll
    for (int i = 0; i < 8; ++i) sfc[i] = rs[i * 32 + lane] + ebias[i * 32 + lane];

    float gs[8];
#pragma unroll
    for (int i = 0; i < 8; ++i) {
        float m1 = sfc[i], m2 = NEG_INF;
#pragma unroll
        for (int off = 16; off > 0; off >>= 1) {
            float o1 = __shfl_xor_sync(0xffffffffu, m1, off);
            float o2 = __shfl_xor_sync(0xffffffffu, m2, off);
            float hi = fmaxf(m1, o1), lo = fminf(m1, o1);
            m1 = hi; m2 = fmaxf(fmaxf(m2, o2), lo);
        }
        gs[i] = m1 + m2;
    }

    unsigned gmask = 0, sel = 0;
    float g4 = 0.0f, g5 = 0.0f;
#pragma unroll
    for (int j = 0; j < 5; ++j) {
        float best = NEG_INF; int bg = 0;
#pragma unroll
        for (int g = 0; g < 8; ++g)
            if (!((sel >> g) & 1u) && gs[g] > best) { best = gs[g]; bg = g; }
        sel |= (1u << bg);
        if (j < 4) gmask |= (1u << bg);
        if (j == 3) g4 = best;
        if (j == 4) g5 = best;
    }

    float cv[8];
#pragma unroll
    for (int i = 0; i < 8; ++i) cv[i] = ((gmask >> i) & 1u) ? sfc[i] : 0.0f;

    unsigned used = 0;
    int idxs[8];
    float mmin = 1e30f, pv = 0.0f;
#pragma unroll
    for (int j = 0; j < 9; ++j) {
        float bv = NEG_INF; int be = 1 << 30;
#pragma unroll
        for (int i = 0; i < 8; ++i) {
            if (!((used >> i) & 1u)) {
                const float v = cv[i];
                const int e = i * 32 + lane;
                if (v > bv || (v == bv && e < be)) { bv = v; be = e; }
            }
        }
#pragma unroll
        for (int off = 16; off > 0; off >>= 1) {
            float ov = __shfl_xor_sync(0xffffffffu, bv, off);
            int oe = __shfl_xor_sync(0xffffffffu, be, off);
            if (ov > bv || (ov == bv && oe < be)) { bv = ov; be = oe; }
        }
        if (j < 8) idxs[j] = be;
        if ((be & 31) == lane) used |= (1u << (be >> 5));
        if (j > 0) mmin = fminf(mmin, pv - bv);
        pv = bv;
    }

    if (check && (mmin < TAU_E || (g4 - g5) < TAU_G)) {
        if (lane == 0) {
            int s = atomicAdd(&g_nflag, 1);
            if (s < RCAP) g_flags[s] = t;
        }
    }

    float wj = 0.0f;
    if (lane < TOPK) wj = rs[idxs[lane]];
    float ssum = wj;
#pragma unroll
    for (int off = 4; off > 0; off >>= 1)
        ssum += __shfl_xor_sync(0xffffffffu, ssum, off);
    const float denom = ssum + 1e-20f;
    if (lane < TOPK) {
        out[(size_t)t * TOPK + lane] = (float)idxs[lane];
        out[(size_t)T * TOPK + (size_t)t * TOPK + lane] = wj / denom * SCALE_F;
    }
}

// ---------- K3: router ----------
__global__ __launch_bounds__(128)
void router_kernel(const float* __restrict__ ebias, float* __restrict__ out, int T)
{
    __shared__ float raw_s[4][NEXP];
    const int warp = threadIdx.x >> 5;
    const int lane = threadIdx.x & 31;
    const int t = blockIdx.x * 4 + warp;
    if (t >= T) return;
    float* rs = raw_s[warp];
#pragma unroll
    for (int i = 0; i < 2; ++i)
        *(float4*)(rs + i * 128 + lane * 4) =
            *(const float4*)(g_scores + (size_t)t * NEXP + i * 128 + lane * 4);
    __syncwarp();
    route_token(rs, ebias, lane, t, T, out, true);
}

// ---------- K4: repair split-K mini-GEMM (exact Kahan partials) ----------
__global__ __launch_bounds__(256, 2)
void repair_gemm_kernel(const float* __restrict__ X, const float* __restrict__ W)
{
    const int nf = min(g_nflag, RCAP);
    const int tile = blockIdx.y;
    if (tile * RTM >= nf) return;
    const int ks = blockIdx.x;

    extern __shared__ float rsm[];
    float* xs = rsm;
    float* ws = rsm + RTM * RKLEN;
    __shared__ int toks[RTM];

    const int tid = threadIdx.x;
    const ull neg1 = pack2(-1.0f, -1.0f);
    const int k0 = ks * RKLEN;

    if (tid < RTM) toks[tid] = g_flags[min(tile * RTM + tid, nf - 1)];
    __syncthreads();

#pragma unroll
    for (int q = 0; q < 8; ++q) {
        const int f4 = tid + 256 * q;
        const int j = f4 >> 7, pos = f4 & 127;
        *(float4*)(xs + j * RKLEN + pos * 4) =
            __ldg((const float4*)(X + (size_t)toks[j] * HDIM + k0 + pos * 4));
    }

    float4 wreg[8];
    auto wload = [&](int c) {
        const int kc = k0 + c * 32;
#pragma unroll
        for (int q = 0; q < 8; ++q) {
            const int f4 = tid + 256 * q;
            const int row = f4 >> 3, c4 = f4 & 7;
            wreg[q] = __ldg((const float4*)(W + (size_t)row * HDIM + kc + c4 * 4));
        }
    };
    auto wstore = [&](int buf) {
        float* wb = ws + buf * RWS_BUF;
#pragma unroll
        for (int q = 0; q < 8; ++q) {
            const int f4 = tid + 256 * q;
            const int row = f4 >> 3, c4 = f4 & 7;
            float* p = wb + row * RWS_STRIDE + c4 * 4;
            p[0] = wreg[q].x; p[1] = wreg[q].y; p[2] = wreg[q].z; p[3] = wreg[q].w;
        }
    };

    ull run[RTM], acc[RTM], cmp[RTM];
#pragma unroll
    for (int j = 0; j < RTM; ++j) { run[j] = 0; acc[j] = 0; cmp[j] = 0; }

    wload(0);
    wstore(0);
    __syncthreads();
    wload(1);

    for (int c = 0; c < RNCH; ++c) {
        const int buf = c & 1;
        const float* wrow = ws + buf * RWS_BUF + tid * RWS_STRIDE;
        const float* xb = xs + c * 32;
#pragma unroll
        for (int u = 0; u < 16; ++u) {
            ull wv = *(const ull*)(wrow + 2 * u);
#pragma unroll
            for (int j = 0; j < RTM; ++j)
                fma2_acc(run[j], wv, *(const ull*)(xb + j * RKLEN + 2 * u));
        }
#pragma unroll
        for (int j = 0; j < RTM; ++j) {
            ull y = fma2(cmp[j], neg1, run[j]);
            ull t2 = add2(acc[j], y);
            ull d = fma2(acc[j], neg1, t2);
            cmp[j] = fma2(y, neg1, d);
            acc[j] = t2;
            run[j] = 0;
        }
        if (c + 1 < RNCH) {
            wstore(buf ^ 1);
            if (c + 2 < RNCH) wload(c + 2);
        }
        __syncthreads();
    }

#pragma unroll
    for (int j = 0; j < RTM; ++j) {
        const int slot = tile * RTM + j;
        if (slot >= nf) break;
        float2 a = unpk2(acc[j]);
        float2 cc = unpk2(cmp[j]);
        float s = a.x + a.y;
        float bp = s - a.x;
        float r = (a.x - (s - bp)) + (a.y - bp);
        float e = r - (cc.x + cc.y);
        g_rep[ks][slot][tid] = make_float2(s, e);
    }
}

// ---------- K5: combine partials exactly, re-route flagged tokens ----------
__global__ __launch_bounds__(256)
void combine_kernel(const float* __restrict__ bvec, const float* __restrict__ ebias,
                    float* __restrict__ out, int T)
{
    __shared__ float sc[8][NEXP];
    const int warp = threadIdx.x >> 5;
    const int lane = threadIdx.x & 31;
    const int nf = min(g_nflag, RCAP);

    for (int slot = blockIdx.x * 8 + warp; slot < nf; slot += gridDim.x * 8) {
        const int t = g_flags[slot];
#pragma unroll
        for (int i = 0; i < 8; ++i) {
            const int e = i * 32 + lane;
            float s = 0.0f, err = 0.0f;
#pragma unroll
            for (int k = 0; k < RKS; ++k) {
                float2 p = g_rep[k][slot][e];
                float t2 = s + p.x;
                float bp = t2 - s;
                float r = (s - (t2 - bp)) + (p.x - bp);
                s = t2;
                err += r + p.y;
            }
            float l = s + (err + bvec[e]);
            sc[warp][e] = 1.0f / (1.0f + expf(-l));
        }
        __syncwarp();
        route_token(sc[warp], ebias, lane, t, T, out, false);
        __syncwarp();
    }
}

extern "C" void kernel_launch(void* const* d_in, const int* in_sizes, int n_in,
                              void* d_out, int out_size)
{
    const float* hs = (const float*)d_in[0];
    const float* W  = (const float*)d_in[1];
    const float* b  = (const float*)d_in[2];
    const float* eb = (const float*)d_in[3];
    const int T = in_sizes[0] / HDIM;

    cudaFuncSetAttribute(gemm_kernel, cudaFuncAttributeMaxDynamicSharedMemorySize, GEMM_SMEM);
    cudaFuncSetAttribute(repair_gemm_kernel, cudaFuncAttributeMaxDynamicSharedMemorySize, REP_SMEM);

    prep_kernel<<<256, 256>>>(W);
    dim3 ggrid(NEXP / BN, T / BM);
    gemm_kernel<<<ggrid, NTHR, GEMM_SMEM>>>(hs, b, T);
    router_kernel<<<(T + 3) / 4, 128>>>(eb, (float*)d_out, T);
    dim3 rgrid(RKS, RCAP / RTM);
    repair_gemm_kernel<<<rgrid, 256, REP_SMEM>>>(hs, W);
    combine_kernel<<<64, 256>>>(b, eb, (float*)d_out, T);
}

// round 13
// speedup vs baseline: 1.1810x; 1.1810x over previous
#include <cuda_runtime.h>
#include <cuda_fp16.h>
#include <mma.h>

using namespace nvcuda;

#define HDIM 7168
#define NEXP 256
#define TOPK 8
#define SCALE_F 2.5f
#define MAX_T 8192
#define TAU_E 1e-5f
#define TAU_G 2e-5f

#define BM 128
#define BN 128
#define BK 64
#define NTHR 512
#define NIT (HDIM / BK)          // 112
#define LDH 72
#define MAT_B (128 * LDH * 2)    // 18432
#define STAGE_B (4 * MAT_B)      // 73728
#define GEMM_SMEM (2 * STAGE_B)  // 147456

// repair mini-GEMM (split-K = 28)
#define RCAP 2048
#define RTM 16
#define RKS 28
#define RKLEN 256
#define RNCH (RKLEN / 32)        // 8
#define RWS_STRIDE 34
#define RWS_BUF (256 * RWS_STRIDE)
#define REP_SMEM ((RTM * RKLEN + 2 * RWS_BUF) * 4)

__device__ __half  g_Whi[NEXP * HDIM];
__device__ __half  g_Wlo[NEXP * HDIM];
__device__ float   g_scores[MAX_T * NEXP];
__device__ int     g_nflag;
__device__ int     g_flags[MAX_T];
__device__ float2  g_rep[RKS][RCAP][NEXP];

typedef unsigned long long ull;

__device__ __forceinline__ ull pack2(float lo, float hi) {
    ull r; asm("mov.b64 %0, {%1, %2};" : "=l"(r) : "f"(lo), "f"(hi)); return r;
}
__device__ __forceinline__ void fma2_acc(ull& acc, ull a, ull b) {
    asm("fma.rn.f32x2 %0, %1, %2, %0;" : "+l"(acc) : "l"(a), "l"(b));
}
__device__ __forceinline__ ull fma2(ull a, ull b, ull c) {
    ull d; asm("fma.rn.f32x2 %0, %1, %2, %3;" : "=l"(d) : "l"(a), "l"(b), "l"(c)); return d;
}
__device__ __forceinline__ ull add2(ull a, ull b) {
    ull d; asm("add.rn.f32x2 %0, %1, %2;" : "=l"(d) : "l"(a), "l"(b)); return d;
}
__device__ __forceinline__ float2 unpk2(ull v) {
    float lo, hi; asm("mov.b64 {%0, %1}, %2;" : "=f"(lo), "=f"(hi) : "l"(v));
    return make_float2(lo, hi);
}
__device__ __forceinline__ unsigned smem_u32(const void* p) {
    unsigned a;
    asm("{ .reg .u64 t; cvta.to.shared.u64 t, %1; cvt.u32.u64 %0, t; }" : "=r"(a) : "l"(p));
    return a;
}
__device__ __forceinline__ void cp_async16(unsigned saddr, const void* gaddr) {
    asm volatile("cp.async.cg.shared.global [%0], [%1], 16;" :: "r"(saddr), "l"(gaddr));
}
#define CP_COMMIT() asm volatile("cp.async.commit_group;" ::: "memory")
#define CP_WAIT0()  asm volatile("cp.async.wait_group 0;" ::: "memory")

// ---------- K1: split W (x256) into fp16 hi/lo; reset flag counter ----------
__global__ void prep_kernel(const float* __restrict__ W) {
    if (blockIdx.x == 0 && threadIdx.x == 0) g_nflag = 0;
    const int total = NEXP * HDIM;
    for (int i = blockIdx.x * blockDim.x + threadIdx.x; i < total;
         i += gridDim.x * blockDim.x) {
        float ws = W[i] * 256.0f;
        __half h = __float2half_rn(ws);
        g_Whi[i] = h;
        g_Wlo[i] = __float2half_rn(ws - __half2float(h));
    }
}

// ---------- K2: wmma fp16 split-2 GEMM, separate hi/corr accumulators ----------
__global__ __launch_bounds__(NTHR, 1)
void gemm_kernel(const float* __restrict__ X, const float* __restrict__ bvec, int T)
{
    extern __shared__ __half sh[];
    const int tid = threadIdx.x;
    const int wid = tid >> 5;
    const int n0 = blockIdx.x * BN;
    const int m0 = blockIdx.y * BM;
    const int wm = wid & 3;
    const int wn = wid >> 2;
    const unsigned sbase = smem_u32(sh);

    wmma::fragment<wmma::accumulator, 16, 16, 16, float> acc_h[2][2], acc_c[2][2];
#pragma unroll
    for (int mt = 0; mt < 2; ++mt)
#pragma unroll
        for (int nt = 0; nt < 2; ++nt) {
            wmma::fill_fragment(acc_h[mt][nt], 0.0f);
            wmma::fill_fragment(acc_c[mt][nt], 0.0f);
        }

    float4 av[4];

    auto avload = [&](int it) {
        const int kc = it * BK;
#pragma unroll
        for (int i = 0; i < 4; ++i) {
            const int idx = tid + NTHR * i;
            const int row = idx >> 4, c4 = idx & 15;
            av[i] = __ldg((const float4*)(X + (size_t)(m0 + row) * HDIM + kc + c4 * 4));
        }
    };
    auto fillA = [&](int stage) {
        __half* Ahi = sh + stage * (STAGE_B / 2);
        __half* Alo = Ahi + MAT_B / 2;
#pragma unroll
        for (int i = 0; i < 4; ++i) {
            const int idx = tid + NTHR * i;
            const int row = idx >> 4, c4 = idx & 15;
            float4 v = av[i];
            __half2 h01 = __floats2half2_rn(v.x, v.y);
            __half2 h23 = __floats2half2_rn(v.z, v.w);
            float2 f01 = __half22float2(h01), f23 = __half22float2(h23);
            __half2 l01 = __floats2half2_rn(v.x - f01.x, v.y - f01.y);
            __half2 l23 = __floats2half2_rn(v.z - f23.x, v.w - f23.y);
            uint2 ph, pl;
            ph.x = reinterpret_cast<unsigned&>(h01); ph.y = reinterpret_cast<unsigned&>(h23);
            pl.x = reinterpret_cast<unsigned&>(l01); pl.y = reinterpret_cast<unsigned&>(l23);
            *(uint2*)(Ahi + row * LDH + c4 * 4) = ph;
            *(uint2*)(Alo + row * LDH + c4 * 4) = pl;
        }
    };
    auto cpB = [&](int it, int stage) {
        const int kc = it * BK;
        const unsigned bhi = sbase + stage * STAGE_B + 2 * MAT_B;
        const unsigned blo = bhi + MAT_B;
#pragma unroll
        for (int i = 0; i < 2; ++i) {
            const int idx = tid + NTHR * i;
            const int row = idx >> 3, c8 = idx & 7;
            const unsigned soff = (row * LDH + c8 * 8) * 2;
            const size_t goff = (size_t)(n0 + row) * HDIM + kc + c8 * 8;
            cp_async16(bhi + soff, g_Whi + goff);
            cp_async16(blo + soff, g_Wlo + goff);
        }
        CP_COMMIT();
    };

    cpB(0, 0);
    avload(0);
    fillA(0);
    avload(1);
    CP_WAIT0();
    __syncthreads();

    for (int it = 0; it < NIT; ++it) {
        const int buf = it & 1;
        if (it + 1 < NIT) cpB(it + 1, buf ^ 1);

        const __half* Ahi = sh + buf * (STAGE_B / 2);
        const __half* Alo = Ahi + MAT_B / 2;
        const __half* Bhi = Alo + MAT_B / 2;
        const __half* Blo = Bhi + MAT_B / 2;
#pragma unroll
        for (int kk = 0; kk < 4; ++kk) {
            wmma::fragment<wmma::matrix_a, 16, 16, 16, __half, wmma::row_major> ah[2], al[2];
#pragma unroll
            for (int mt = 0; mt < 2; ++mt) {
                const int r = wm * 32 + mt * 16;
                wmma::load_matrix_sync(ah[mt], Ahi + r * LDH + kk * 16, LDH);
                wmma::load_matrix_sync(al[mt], Alo + r * LDH + kk * 16, LDH);
            }
#pragma unroll
            for (int nt = 0; nt < 2; ++nt) {
                const int c = wn * 32 + nt * 16;
                wmma::fragment<wmma::matrix_b, 16, 16, 16, __half, wmma::col_major> fbh, fbl;
                wmma::load_matrix_sync(fbh, Bhi + c * LDH + kk * 16, LDH);
                wmma::load_matrix_sync(fbl, Blo + c * LDH + kk * 16, LDH);
#pragma unroll
                for (int mt = 0; mt < 2; ++mt) {
                    wmma::mma_sync(acc_h[mt][nt], ah[mt], fbh, acc_h[mt][nt]);
                    wmma::mma_sync(acc_c[mt][nt], ah[mt], fbl, acc_c[mt][nt]);
                    wmma::mma_sync(acc_c[mt][nt], al[mt], fbh, acc_c[mt][nt]);
                }
            }
        }
        if (it + 1 < NIT) {
            fillA(buf ^ 1);
            if (it + 2 < NIT) avload(it + 2);
            CP_WAIT0();
        }
        __syncthreads();
    }

    // merge correction into main accumulator (element-wise; same fragment layout)
#pragma unroll
    for (int mt = 0; mt < 2; ++mt)
#pragma unroll
        for (int nt = 0; nt < 2; ++nt)
#pragma unroll
            for (int e = 0; e < acc_h[mt][nt].num_elements; ++e)
                acc_h[mt][nt].x[e] += acc_c[mt][nt].x[e];

    float* sacc = (float*)sh;
#pragma unroll
    for (int mt = 0; mt < 2; ++mt)
#pragma unroll
        for (int nt = 0; nt < 2; ++nt)
            wmma::store_matrix_sync(sacc + (wm * 32 + mt * 16) * 128 + wn * 32 + nt * 16,
                                    acc_h[mt][nt], 128, wmma::mem_row_major);
    __syncthreads();
#pragma unroll
    for (int i = 0; i < 8; ++i) {
        const int idx = tid + NTHR * i;
        const int row = idx >> 5, c4 = idx & 31;
        float4 v = *(float4*)(sacc + row * 128 + c4 * 4);
        const int n = n0 + c4 * 4;
        float4 o;
        o.x = 1.0f / (1.0f + expf(-(v.x * (1.0f/256.0f) + bvec[n])));
        o.y = 1.0f / (1.0f + expf(-(v.y * (1.0f/256.0f) + bvec[n+1])));
        o.z = 1.0f / (1.0f + expf(-(v.z * (1.0f/256.0f) + bvec[n+2])));
        o.w = 1.0f / (1.0f + expf(-(v.w * (1.0f/256.0f) + bvec[n+3])));
        *(float4*)(g_scores + (size_t)(m0 + row) * NEXP + n) = o;
    }
}

// ---------- warp-collective routing core ----------
__device__ __forceinline__ void route_token(const float* __restrict__ rs,
                                            const float* __restrict__ ebias,
                                            int lane, int t, int T,
                                            float* __restrict__ out, bool check)
{
    const float NEG_INF = -1e30f;
    float sfc[8];
#pragma unroll
    for (int i = 0; i < 8; ++i) sfc[i] = rs[i * 32 + lane] + ebias[i * 32 + lane];

    float gs[8];
#pragma unroll
    for (int i = 0; i < 8; ++i) {
        float m1 = sfc[i], m2 = NEG_INF;
#pragma unroll
        for (int off = 16; off > 0; off >>= 1) {
            float o1 = __shfl_xor_sync(0xffffffffu, m1, off);
            float o2 = __shfl_xor_sync(0xffffffffu, m2, off);
            float hi = fmaxf(m1, o1), lo = fminf(m1, o1);
            m1 = hi; m2 = fmaxf(fmaxf(m2, o2), lo);
        }
        gs[i] = m1 + m2;
    }

    unsigned gmask = 0, sel = 0;
    float g4 = 0.0f, g5 = 0.0f;
#pragma unroll
    for (int j = 0; j < 5; ++j) {
        float best = NEG_INF; int bg = 0;
#pragma unroll
        for (int g = 0; g < 8; ++g)
            if (!((sel >> g) & 1u) && gs[g] > best) { best = gs[g]; bg = g; }
        sel |= (1u << bg);
        if (j < 4) gmask |= (1u << bg);
        if (j == 3) g4 = best;
        if (j == 4) g5 = best;
    }

    float cv[8];
#pragma unroll
    for (int i = 0; i < 8; ++i) cv[i] = ((gmask >> i) & 1u) ? sfc[i] : 0.0f;

    unsigned used = 0;
    int idxs[8];
    float mmin = 1e30f, pv = 0.0f;
#pragma unroll
    for (int j = 0; j < 9; ++j) {
        float bv = NEG_INF; int be = 1 << 30;
#pragma unroll
        for (int i = 0; i < 8; ++i) {
            if (!((used >> i) & 1u)) {
                const float v = cv[i];
                const int e = i * 32 + lane;
                if (v > bv || (v == bv && e < be)) { bv = v; be = e; }
            }
        }
#pragma unroll
        for (int off = 16; off > 0; off >>= 1) {
            float ov = __shfl_xor_sync(0xffffffffu, bv, off);
            int oe = __shfl_xor_sync(0xffffffffu, be, off);
            if (ov > bv || (ov == bv && oe < be)) { bv = ov; be = oe; }
        }
        if (j < 8) idxs[j] = be;
        if ((be & 31) == lane) used |= (1u << (be >> 5));
        if (j > 0) mmin = fminf(mmin, pv - bv);
        pv = bv;
    }

    if (check && (mmin < TAU_E || (g4 - g5) < TAU_G)) {
        if (lane == 0) {
            int s = atomicAdd(&g_nflag, 1);
            if (s < RCAP) g_flags[s] = t;
        }
    }

    float wj = 0.0f;
    if (lane < TOPK) wj = rs[idxs[lane]];
    float ssum = wj;
#pragma unroll
    for (int off = 4; off > 0; off >>= 1)
        ssum += __shfl_xor_sync(0xffffffffu, ssum, off);
    const float denom = ssum + 1e-20f;
    if (lane < TOPK) {
        out[(size_t)t * TOPK + lane] = (float)idxs[lane];
        out[(size_t)T * TOPK + (size_t)t * TOPK + lane] = wj / denom * SCALE_F;
    }
}

// ---------- K3: router ----------
__global__ __launch_bounds__(128)
void router_kernel(const float* __restrict__ ebias, float* __restrict__ out, int T)
{
    __shared__ float raw_s[4][NEXP];
    const int warp = threadIdx.x >> 5;
    const int lane = threadIdx.x & 31;
    const int t = blockIdx.x * 4 + warp;
    if (t >= T) return;
    float* rs = raw_s[warp];
#pragma unroll
    for (int i = 0; i < 2; ++i)
        *(float4*)(rs + i * 128 + lane * 4) =
            *(const float4*)(g_scores + (size_t)t * NEXP + i * 128 + lane * 4);
    __syncwarp();
    route_token(rs, ebias, lane, t, T, out, true);
}

// ---------- K4: repair split-K mini-GEMM (exact Kahan partials) ----------
__global__ __launch_bounds__(256, 2)
void repair_gemm_kernel(const float* __restrict__ X, const float* __restrict__ W)
{
    const int nf = min(g_nflag, RCAP);
    const int tile = blockIdx.y;
    if (tile * RTM >= nf) return;
    const int ks = blockIdx.x;

    extern __shared__ float rsm[];
    float* xs = rsm;                     // [RTM][RKLEN] = 16 KB
    float* ws = rsm + RTM * RKLEN;       // [2][256][RWS_STRIDE]
    __shared__ int toks[RTM];

    const int tid = threadIdx.x;
    const ull neg1 = pack2(-1.0f, -1.0f);
    const int k0 = ks * RKLEN;

    if (tid < RTM) toks[tid] = g_flags[min(tile * RTM + tid, nf - 1)];
    __syncthreads();

    // stage x slices: RTM*RKLEN/4 = 1024 float4
#pragma unroll
    for (int q = 0; q < 4; ++q) {
        const int f4 = tid + 256 * q;
        const int j = f4 >> 6, pos = f4 & 63;
        *(float4*)(xs + j * RKLEN + pos * 4) =
            __ldg((const float4*)(X + (size_t)toks[j] * HDIM + k0 + pos * 4));
    }

    float4 wreg[8];
    auto wload = [&](int c) {
        const int kc = k0 + c * 32;
#pragma unroll
        for (int q = 0; q < 8; ++q) {
            const int f4 = tid + 256 * q;
            const int row = f4 >> 3, c4 = f4 & 7;
            wreg[q] = __ldg((const float4*)(W + (size_t)row * HDIM + kc + c4 * 4));
        }
    };
    auto wstore = [&](int buf) {
        float* wb = ws + buf * RWS_BUF;
#pragma unroll
        for (int q = 0; q < 8; ++q) {
            const int f4 = tid + 256 * q;
            const int row = f4 >> 3, c4 = f4 & 7;
            float* p = wb + row * RWS_STRIDE + c4 * 4;
            p[0] = wreg[q].x; p[1] = wreg[q].y; p[2] = wreg[q].z; p[3] = wreg[q].w;
        }
    };

    ull run[RTM], acc[RTM], cmp[RTM];
#pragma unroll
    for (int j = 0; j < RTM; ++j) { run[j] = 0; acc[j] = 0; cmp[j] = 0; }

    wload(0);
    wstore(0);
    __syncthreads();
    wload(1);

    for (int c = 0; c < RNCH; ++c) {
        const int buf = c & 1;
        const float* wrow = ws + buf * RWS_BUF + tid * RWS_STRIDE;
        const float* xb = xs + c * 32;
#pragma unroll
        for (int u = 0; u < 16; ++u) {
            ull wv = *(const ull*)(wrow + 2 * u);
#pragma unroll
            for (int j = 0; j < RTM; ++j)
                fma2_acc(run[j], wv, *(const ull*)(xb + j * RKLEN + 2 * u));
        }
#pragma unroll
        for (int j = 0; j < RTM; ++j) {
            ull y = fma2(cmp[j], neg1, run[j]);
            ull t2 = add2(acc[j], y);
            ull d = fma2(acc[j], neg1, t2);
            cmp[j] = fma2(y, neg1, d);
            acc[j] = t2;
            run[j] = 0;
        }
        if (c + 1 < RNCH) {
            wstore(buf ^ 1);
            if (c + 2 < RNCH) wload(c + 2);
        }
        __syncthreads();
    }

#pragma unroll
    for (int j = 0; j < RTM; ++j) {
        const int slot = tile * RTM + j;
        if (slot >= nf) break;
        float2 a = unpk2(acc[j]);
        float2 cc = unpk2(cmp[j]);
        float s = a.x + a.y;
        float bp = s - a.x;
        float r = (a.x - (s - bp)) + (a.y - bp);
        float e = r - (cc.x + cc.y);
        g_rep[ks][slot][tid] = make_float2(s, e);
    }
}

// ---------- K5: combine partials exactly, re-route flagged tokens ----------
__global__ __launch_bounds__(256)
void combine_kernel(const float* __restrict__ bvec, const float* __restrict__ ebias,
                    float* __restrict__ out, int T)
{
    __shared__ float sc[8][NEXP];
    const int warp = threadIdx.x >> 5;
    const int lane = threadIdx.x & 31;
    const int nf = min(g_nflag, RCAP);

    for (int slot = blockIdx.x * 8 + warp; slot < nf; slot += gridDim.x * 8) {
        const int t = g_flags[slot];
#pragma unroll
        for (int i = 0; i < 8; ++i) {
            const int e = i * 32 + lane;
            float s = 0.0f, err = 0.0f;
#pragma unroll
            for (int k = 0; k < RKS; ++k) {
                float2 p = g_rep[k][slot][e];
                float t2 = s + p.x;
                float bp = t2 - s;
                float r = (s - (t2 - bp)) + (p.x - bp);
                s = t2;
                err += r + p.y;
            }
            float l = s + (err + bvec[e]);
            sc[warp][e] = 1.0f / (1.0f + expf(-l));
        }
        __syncwarp();
        route_token(sc[warp], ebias, lane, t, T, out, false);
        __syncwarp();
    }
}

extern "C" void kernel_launch(void* const* d_in, const int* in_sizes, int n_in,
                              void* d_out, int out_size)
{
    const float* hs = (const float*)d_in[0];
    const float* W  = (const float*)d_in[1];
    const float* b  = (const float*)d_in[2];
    const float* eb = (const float*)d_in[3];
    const int T = in_sizes[0] / HDIM;

    cudaFuncSetAttribute(gemm_kernel, cudaFuncAttributeMaxDynamicSharedMemorySize, GEMM_SMEM);
    cudaFuncSetAttribute(repair_gemm_kernel, cudaFuncAttributeMaxDynamicSharedMemorySize, REP_SMEM);

    prep_kernel<<<256, 256>>>(W);
    dim3 ggrid(NEXP / BN, T / BM);
    gemm_kernel<<<ggrid, NTHR, GEMM_SMEM>>>(hs, b, T);
    router_kernel<<<(T + 3) / 4, 128>>>(eb, (float*)d_out, T);
    dim3 rgrid(RKS, RCAP / RTM);
    repair_gemm_kernel<<<rgrid, 256, REP_SMEM>>>(hs, W);
    combine_kernel<<<64, 256>>>(b, eb, (float*)d_out, T);
}

// round 14
// speedup vs baseline: 1.2277x; 1.0396x over previous
#include <cuda_runtime.h>
#include <cuda_fp16.h>
#include <mma.h>

using namespace nvcuda;

#define HDIM 7168
#define NEXP 256
#define TOPK 8
#define SCALE_F 2.5f
#define MAX_T 8192
#define TAU_E 1e-5f
#define TAU_G 2e-5f

#define BM 128
#define BN 128
#define BK 64
#define NTHR 512
#define NIT (HDIM / BK)          // 112
#define LDH 72
#define MAT_B (128 * LDH * 2)    // 18432
#define STAGE_B (4 * MAT_B)      // 73728
#define GEMM_SMEM (2 * STAGE_B)  // 147456

// repair mini-GEMM (split-K = 28)
#define RCAP 2048
#define RTM 16
#define RKS 28
#define RKLEN 256
#define RNCH (RKLEN / 32)        // 8
#define RWS_STRIDE 34
#define RWS_BUF (256 * RWS_STRIDE)
#define REP_SMEM ((RTM * RKLEN + 2 * RWS_BUF) * 4)

__device__ __half  g_Whi[NEXP * HDIM];
__device__ __half  g_Wlo[NEXP * HDIM];
__device__ float   g_scores[MAX_T * NEXP];
__device__ int     g_nflag;
__device__ int     g_flags[MAX_T];
__device__ float2  g_rep[RKS][RCAP][NEXP];

typedef unsigned long long ull;

__device__ __forceinline__ ull pack2(float lo, float hi) {
    ull r; asm("mov.b64 %0, {%1, %2};" : "=l"(r) : "f"(lo), "f"(hi)); return r;
}
__device__ __forceinline__ void fma2_acc(ull& acc, ull a, ull b) {
    asm("fma.rn.f32x2 %0, %1, %2, %0;" : "+l"(acc) : "l"(a), "l"(b));
}
__device__ __forceinline__ ull fma2(ull a, ull b, ull c) {
    ull d; asm("fma.rn.f32x2 %0, %1, %2, %3;" : "=l"(d) : "l"(a), "l"(b), "l"(c)); return d;
}
__device__ __forceinline__ ull add2(ull a, ull b) {
    ull d; asm("add.rn.f32x2 %0, %1, %2;" : "=l"(d) : "l"(a), "l"(b)); return d;
}
__device__ __forceinline__ float2 unpk2(ull v) {
    float lo, hi; asm("mov.b64 {%0, %1}, %2;" : "=f"(lo), "=f"(hi) : "l"(v));
    return make_float2(lo, hi);
}
__device__ __forceinline__ unsigned smem_u32(const void* p) {
    unsigned a;
    asm("{ .reg .u64 t; cvta.to.shared.u64 t, %1; cvt.u32.u64 %0, t; }" : "=r"(a) : "l"(p));
    return a;
}
__device__ __forceinline__ void cp_async16(unsigned saddr, const void* gaddr) {
    asm volatile("cp.async.cg.shared.global [%0], [%1], 16;" :: "r"(saddr), "l"(gaddr));
}
#define CP_COMMIT() asm volatile("cp.async.commit_group;" ::: "memory")
#define CP_WAIT0()  asm volatile("cp.async.wait_group 0;" ::: "memory")

// ---------- K1: split W (x256) into fp16 hi/lo; reset flag counter ----------
__global__ void prep_kernel(const float* __restrict__ W) {
    if (blockIdx.x == 0 && threadIdx.x == 0) g_nflag = 0;
    const int total = NEXP * HDIM;
    for (int i = blockIdx.x * blockDim.x + threadIdx.x; i < total;
         i += gridDim.x * blockDim.x) {
        float ws = W[i] * 256.0f;
        __half h = __float2half_rn(ws);
        g_Whi[i] = h;
        g_Wlo[i] = __float2half_rn(ws - __half2float(h));
    }
}

// ---------- K2: wmma fp16 split-2 GEMM + bias + sigmoid (512 threads) ----------
__global__ __launch_bounds__(NTHR, 1)
void gemm_kernel(const float* __restrict__ X, const float* __restrict__ bvec, int T)
{
    extern __shared__ __half sh[];
    const int tid = threadIdx.x;
    const int wid = tid >> 5;
    const int n0 = blockIdx.x * BN;
    const int m0 = blockIdx.y * BM;
    const int wm = wid & 3;          // 4 m-warps (32 rows each)
    const int wn = wid >> 2;         // 4 n-warps (32 cols each)
    const unsigned sbase = smem_u32(sh);

    wmma::fragment<wmma::accumulator, 16, 16, 16, float> acc[2][2];
#pragma unroll
    for (int mt = 0; mt < 2; ++mt)
#pragma unroll
        for (int nt = 0; nt < 2; ++nt) wmma::fill_fragment(acc[mt][nt], 0.0f);

    float4 av[4];

    auto avload = [&](int it) {
        const int kc = it * BK;
#pragma unroll
        for (int i = 0; i < 4; ++i) {
            const int idx = tid + NTHR * i;
            const int row = idx >> 4, c4 = idx & 15;
            av[i] = __ldg((const float4*)(X + (size_t)(m0 + row) * HDIM + kc + c4 * 4));
        }
    };
    auto fillA = [&](int stage) {
        __half* Ahi = sh + stage * (STAGE_B / 2);
        __half* Alo = Ahi + MAT_B / 2;
#pragma unroll
        for (int i = 0; i < 4; ++i) {
            const int idx = tid + NTHR * i;
            const int row = idx >> 4, c4 = idx & 15;
            float4 v = av[i];
            __half2 h01 = __floats2half2_rn(v.x, v.y);
            __half2 h23 = __floats2half2_rn(v.z, v.w);
            float2 f01 = __half22float2(h01), f23 = __half22float2(h23);
            __half2 l01 = __floats2half2_rn(v.x - f01.x, v.y - f01.y);
            __half2 l23 = __floats2half2_rn(v.z - f23.x, v.w - f23.y);
            uint2 ph, pl;
            ph.x = reinterpret_cast<unsigned&>(h01); ph.y = reinterpret_cast<unsigned&>(h23);
            pl.x = reinterpret_cast<unsigned&>(l01); pl.y = reinterpret_cast<unsigned&>(l23);
            *(uint2*)(Ahi + row * LDH + c4 * 4) = ph;
            *(uint2*)(Alo + row * LDH + c4 * 4) = pl;
        }
    };
    auto cpB = [&](int it, int stage) {
        const int kc = it * BK;
        const unsigned bhi = sbase + stage * STAGE_B + 2 * MAT_B;
        const unsigned blo = bhi + MAT_B;
#pragma unroll
        for (int i = 0; i < 2; ++i) {
            const int idx = tid + NTHR * i;
            const int row = idx >> 3, c8 = idx & 7;
            const unsigned soff = (row * LDH + c8 * 8) * 2;
            const size_t goff = (size_t)(n0 + row) * HDIM + kc + c8 * 8;
            cp_async16(bhi + soff, g_Whi + goff);
            cp_async16(blo + soff, g_Wlo + goff);
        }
        CP_COMMIT();
    };

    cpB(0, 0);
    avload(0);
    fillA(0);
    avload(1);
    CP_WAIT0();
    __syncthreads();

    for (int it = 0; it < NIT; ++it) {
        const int buf = it & 1;
        if (it + 1 < NIT) cpB(it + 1, buf ^ 1);

        const __half* Ahi = sh + buf * (STAGE_B / 2);
        const __half* Alo = Ahi + MAT_B / 2;
        const __half* Bhi = Alo + MAT_B / 2;
        const __half* Blo = Bhi + MAT_B / 2;
#pragma unroll
        for (int kk = 0; kk < 4; ++kk) {
            wmma::fragment<wmma::matrix_a, 16, 16, 16, __half, wmma::row_major> ah[2], al[2];
#pragma unroll
            for (int mt = 0; mt < 2; ++mt) {
                const int r = wm * 32 + mt * 16;
                wmma::load_matrix_sync(ah[mt], Ahi + r * LDH + kk * 16, LDH);
                wmma::load_matrix_sync(al[mt], Alo + r * LDH + kk * 16, LDH);
            }
#pragma unroll
            for (int nt = 0; nt < 2; ++nt) {
                const int c = wn * 32 + nt * 16;
                wmma::fragment<wmma::matrix_b, 16, 16, 16, __half, wmma::col_major> fbh, fbl;
                wmma::load_matrix_sync(fbh, Bhi + c * LDH + kk * 16, LDH);
                wmma::load_matrix_sync(fbl, Blo + c * LDH + kk * 16, LDH);
#pragma unroll
                for (int mt = 0; mt < 2; ++mt) {
                    wmma::mma_sync(acc[mt][nt], ah[mt], fbh, acc[mt][nt]);
                    wmma::mma_sync(acc[mt][nt], ah[mt], fbl, acc[mt][nt]);
                    wmma::mma_sync(acc[mt][nt], al[mt], fbh, acc[mt][nt]);
                }
            }
        }
        if (it + 1 < NIT) {
            fillA(buf ^ 1);                  // av regs hold it+1
            if (it + 2 < NIT) avload(it + 2);
            CP_WAIT0();
        }
        __syncthreads();
    }

    float* sacc = (float*)sh;
#pragma unroll
    for (int mt = 0; mt < 2; ++mt)
#pragma unroll
        for (int nt = 0; nt < 2; ++nt)
            wmma::store_matrix_sync(sacc + (wm * 32 + mt * 16) * 128 + wn * 32 + nt * 16,
                                    acc[mt][nt], 128, wmma::mem_row_major);
    __syncthreads();
#pragma unroll
    for (int i = 0; i < 8; ++i) {
        const int idx = tid + NTHR * i;
        const int row = idx >> 5, c4 = idx & 31;
        float4 v = *(float4*)(sacc + row * 128 + c4 * 4);
        const int n = n0 + c4 * 4;
        float4 o;
        o.x = 1.0f / (1.0f + expf(-(v.x * (1.0f/256.0f) + bvec[n])));
        o.y = 1.0f / (1.0f + expf(-(v.y * (1.0f/256.0f) + bvec[n+1])));
        o.z = 1.0f / (1.0f + expf(-(v.z * (1.0f/256.0f) + bvec[n+2])));
        o.w = 1.0f / (1.0f + expf(-(v.w * (1.0f/256.0f) + bvec[n+3])));
        *(float4*)(g_scores + (size_t)(m0 + row) * NEXP + n) = o;
    }
}

// ---------- warp-collective routing core ----------
__device__ __forceinline__ void route_token(const float* __restrict__ rs,
                                            const float* __restrict__ ebias,
                                            int lane, int t, int T,
                                            float* __restrict__ out, bool check)
{
    const float NEG_INF = -1e30f;
    float sfc[8];
#pragma unroll
    for (int i = 0; i < 8; ++i) sfc[i] = rs[i * 32 + lane] + ebias[i * 32 + lane];

    float gs[8];
#pragma unroll
    for (int i = 0; i < 8; ++i) {
        float m1 = sfc[i], m2 = NEG_INF;
#pragma unroll
        for (int off = 16; off > 0; off >>= 1) {
            float o1 = __shfl_xor_sync(0xffffffffu, m1, off);
            float o2 = __shfl_xor_sync(0xffffffffu, m2, off);
            float hi = fmaxf(m1, o1), lo = fminf(m1, o1);
            m1 = hi; m2 = fmaxf(fmaxf(m2, o2), lo);
        }
        gs[i] = m1 + m2;
    }

    unsigned gmask = 0, sel = 0;
    float g4 = 0.0f, g5 = 0.0f;
#pragma unroll
    for (int j = 0; j < 5; ++j) {
        float best = NEG_INF; int bg = 0;
#pragma unroll
        for (int g = 0; g < 8; ++g)
            if (!((sel >> g) & 1u) && gs[g] > best) { best = gs[g]; bg = g; }
        sel |= (1u << bg);
        if (j < 4) gmask |= (1u << bg);
        if (j == 3) g4 = best;
        if (j == 4) g5 = best;
    }

    float cv[8];
#pragma unroll
    for (int i = 0; i < 8; ++i) cv[i] = ((gmask >> i) & 1u) ? sfc[i] : 0.0f;

    unsigned used = 0;
    int idxs[8];
    float mmin = 1e30f, pv = 0.0f;
#pragma unroll
    for (int j = 0; j < 9; ++j) {
        float bv = NEG_INF; int be = 1 << 30;
#pragma unroll
        for (int i = 0; i < 8; ++i) {
            if (!((used >> i) & 1u)) {
                const float v = cv[i];
                const int e = i * 32 + lane;
                if (v > bv || (v == bv && e < be)) { bv = v; be = e; }
            }
        }
#pragma unroll
        for (int off = 16; off > 0; off >>= 1) {
            float ov = __shfl_xor_sync(0xffffffffu, bv, off);
            int oe = __shfl_xor_sync(0xffffffffu, be, off);
            if (ov > bv || (ov == bv && oe < be)) { bv = ov; be = oe; }
        }
        if (j < 8) idxs[j] = be;
        if ((be & 31) == lane) used |= (1u << (be >> 5));
        if (j > 0) mmin = fminf(mmin, pv - bv);
        pv = bv;
    }

    if (check && (mmin < TAU_E || (g4 - g5) < TAU_G)) {
        if (lane == 0) {
            int s = atomicAdd(&g_nflag, 1);
            if (s < RCAP) g_flags[s] = t;
        }
    }

    float wj = 0.0f;
    if (lane < TOPK) wj = rs[idxs[lane]];
    float ssum = wj;
#pragma unroll
    for (int off = 4; off > 0; off >>= 1)
        ssum += __shfl_xor_sync(0xffffffffu, ssum, off);
    const float denom = ssum + 1e-20f;
    if (lane < TOPK) {
        out[(size_t)t * TOPK + lane] = (float)idxs[lane];
        out[(size_t)T * TOPK + (size_t)t * TOPK + lane] = wj / denom * SCALE_F;
    }
}

// ---------- K3: router ----------
__global__ __launch_bounds__(128)
void router_kernel(const float* __restrict__ ebias, float* __restrict__ out, int T)
{
    __shared__ float raw_s[4][NEXP];
    const int warp = threadIdx.x >> 5;
    const int lane = threadIdx.x & 31;
    const int t = blockIdx.x * 4 + warp;
    if (t >= T) return;
    float* rs = raw_s[warp];
#pragma unroll
    for (int i = 0; i < 2; ++i)
        *(float4*)(rs + i * 128 + lane * 4) =
            *(const float4*)(g_scores + (size_t)t * NEXP + i * 128 + lane * 4);
    __syncwarp();
    route_token(rs, ebias, lane, t, T, out, true);
}

// ---------- K4: repair split-K mini-GEMM (exact Kahan partials) ----------
__global__ __launch_bounds__(256, 2)
void repair_gemm_kernel(const float* __restrict__ X, const float* __restrict__ W)
{
    const int nf = min(g_nflag, RCAP);
    const int tile = blockIdx.y;
    if (tile * RTM >= nf) return;
    const int ks = blockIdx.x;

    extern __shared__ float rsm[];
    float* xs = rsm;                     // [RTM][RKLEN] = 16 KB
    float* ws = rsm + RTM * RKLEN;       // [2][256][RWS_STRIDE]
    __shared__ int toks[RTM];

    const int tid = threadIdx.x;
    const ull neg1 = pack2(-1.0f, -1.0f);
    const int k0 = ks * RKLEN;

    if (tid < RTM) toks[tid] = g_flags[min(tile * RTM + tid, nf - 1)];
    __syncthreads();

#pragma unroll
    for (int q = 0; q < 4; ++q) {
        const int f4 = tid + 256 * q;
        const int j = f4 >> 6, pos = f4 & 63;
        *(float4*)(xs + j * RKLEN + pos * 4) =
            __ldg((const float4*)(X + (size_t)toks[j] * HDIM + k0 + pos * 4));
    }

    float4 wreg[8];
    auto wload = [&](int c) {
        const int kc = k0 + c * 32;
#pragma unroll
        for (int q = 0; q < 8; ++q) {
            const int f4 = tid + 256 * q;
            const int row = f4 >> 3, c4 = f4 & 7;
            wreg[q] = __ldg((const float4*)(W + (size_t)row * HDIM + kc + c4 * 4));
        }
    };
    auto wstore = [&](int buf) {
        float* wb = ws + buf * RWS_BUF;
#pragma unroll
        for (int q = 0; q < 8; ++q) {
            const int f4 = tid + 256 * q;
            const int row = f4 >> 3, c4 = f4 & 7;
            float* p = wb + row * RWS_STRIDE + c4 * 4;
            p[0] = wreg[q].x; p[1] = wreg[q].y; p[2] = wreg[q].z; p[3] = wreg[q].w;
        }
    };

    ull run[RTM], acc[RTM], cmp[RTM];
#pragma unroll
    for (int j = 0; j < RTM; ++j) { run[j] = 0; acc[j] = 0; cmp[j] = 0; }

    wload(0);
    wstore(0);
    __syncthreads();
    wload(1);

    for (int c = 0; c < RNCH; ++c) {
        const int buf = c & 1;
        const float* wrow = ws + buf * RWS_BUF + tid * RWS_STRIDE;
        const float* xb = xs + c * 32;
#pragma unroll
        for (int u = 0; u < 16; ++u) {
            ull wv = *(const ull*)(wrow + 2 * u);
#pragma unroll
            for (int j = 0; j < RTM; ++j)
                fma2_acc(run[j], wv, *(const ull*)(xb + j * RKLEN + 2 * u));
        }
#pragma unroll
        for (int j = 0; j < RTM; ++j) {
            ull y = fma2(cmp[j], neg1, run[j]);
            ull t2 = add2(acc[j], y);
            ull d = fma2(acc[j], neg1, t2);
            cmp[j] = fma2(y, neg1, d);
            acc[j] = t2;
            run[j] = 0;
        }
        if (c + 1 < RNCH) {
            wstore(buf ^ 1);
            if (c + 2 < RNCH) wload(c + 2);
        }
        __syncthreads();
    }

#pragma unroll
    for (int j = 0; j < RTM; ++j) {
        const int slot = tile * RTM + j;
        if (slot >= nf) break;
        float2 a = unpk2(acc[j]);
        float2 cc = unpk2(cmp[j]);
        float s = a.x + a.y;
        float bp = s - a.x;
        float r = (a.x - (s - bp)) + (a.y - bp);
        float e = r - (cc.x + cc.y);
        g_rep[ks][slot][tid] = make_float2(s, e);
    }
}

// ---------- K5: combine partials exactly, re-route flagged tokens ----------
__global__ __launch_bounds__(256)
void combine_kernel(const float* __restrict__ bvec, const float* __restrict__ ebias,
                    float* __restrict__ out, int T)
{
    __shared__ float sc[8][NEXP];
    const int warp = threadIdx.x >> 5;
    const int lane = threadIdx.x & 31;
    const int nf = min(g_nflag, RCAP);

    for (int slot = blockIdx.x * 8 + warp; slot < nf; slot += gridDim.x * 8) {
        const int t = g_flags[slot];
#pragma unroll
        for (int i = 0; i < 8; ++i) {
            const int e = i * 32 + lane;
            float s = 0.0f, err = 0.0f;
#pragma unroll
            for (int k = 0; k < RKS; ++k) {
                float2 p = g_rep[k][slot][e];
                float t2 = s + p.x;
                float bp = t2 - s;
                float r = (s - (t2 - bp)) + (p.x - bp);
                s = t2;
                err += r + p.y;
            }
            float l = s + (err + bvec[e]);
            sc[warp][e] = 1.0f / (1.0f + expf(-l));
        }
        __syncwarp();
        route_token(sc[warp], ebias, lane, t, T, out, false);
        __syncwarp();
    }
}

extern "C" void kernel_launch(void* const* d_in, const int* in_sizes, int n_in,
                              void* d_out, int out_size)
{
    const float* hs = (const float*)d_in[0];
    const float* W  = (const float*)d_in[1];
    const float* b  = (const float*)d_in[2];
    const float* eb = (const float*)d_in[3];
    const int T = in_sizes[0] / HDIM;

    cudaFuncSetAttribute(gemm_kernel, cudaFuncAttributeMaxDynamicSharedMemorySize, GEMM_SMEM);
    cudaFuncSetAttribute(repair_gemm_kernel, cudaFuncAttributeMaxDynamicSharedMemorySize, REP_SMEM);

    prep_kernel<<<256, 256>>>(W);
    dim3 ggrid(NEXP / BN, T / BM);
    gemm_kernel<<<ggrid, NTHR, GEMM_SMEM>>>(hs, b, T);
    router_kernel<<<(T + 3) / 4, 128>>>(eb, (float*)d_out, T);
    dim3 rgrid(RKS, RCAP / RTM);
    repair_gemm_kernel<<<rgrid, 256, REP_SMEM>>>(hs, W);
    combine_kernel<<<64, 256>>>(b, eb, (float*)d_out, T);
}

// round 15
// speedup vs baseline: 1.2717x; 1.0358x over previous
#include <cuda_runtime.h>
#include <cuda_fp16.h>
#include <mma.h>

using namespace nvcuda;

#define HDIM 7168
#define NEXP 256
#define TOPK 8
#define SCALE_F 2.5f
#define MAX_T 8192
#define TAU_E 1e-5f
#define TAU_G 2e-5f

#define BM 128
#define BN 128
#define BK 64
#define NTHR 512
#define NIT (HDIM / BK)          // 112
#define LDH 72
#define MAT_B (128 * LDH * 2)    // 18432
#define STAGE_B (4 * MAT_B)      // 73728
#define GEMM_SMEM (2 * STAGE_B)  // 147456

// repair mini-GEMM (split-K = 28, tile-stride grid)
#define RCAP 2048
#define RTM 16
#define RKS 28
#define RKLEN 256
#define RNCH (RKLEN / 32)        // 8
#define RTILES 8                 // grid.y; blocks stride over token tiles
#define RWS_STRIDE 34
#define RWS_BUF (256 * RWS_STRIDE)
#define REP_SMEM ((RTM * RKLEN + 2 * RWS_BUF) * 4)

__device__ __half  g_Whi[NEXP * HDIM];
__device__ __half  g_Wlo[NEXP * HDIM];
__device__ float   g_scores[MAX_T * NEXP];
__device__ int     g_nflag;
__device__ int     g_flags[MAX_T];
__device__ float2  g_rep[RKS][RCAP][NEXP];

typedef unsigned long long ull;

__device__ __forceinline__ ull pack2(float lo, float hi) {
    ull r; asm("mov.b64 %0, {%1, %2};" : "=l"(r) : "f"(lo), "f"(hi)); return r;
}
__device__ __forceinline__ void fma2_acc(ull& acc, ull a, ull b) {
    asm("fma.rn.f32x2 %0, %1, %2, %0;" : "+l"(acc) : "l"(a), "l"(b));
}
__device__ __forceinline__ ull fma2(ull a, ull b, ull c) {
    ull d; asm("fma.rn.f32x2 %0, %1, %2, %3;" : "=l"(d) : "l"(a), "l"(b), "l"(c)); return d;
}
__device__ __forceinline__ ull add2(ull a, ull b) {
    ull d; asm("add.rn.f32x2 %0, %1, %2;" : "=l"(d) : "l"(a), "l"(b)); return d;
}
__device__ __forceinline__ float2 unpk2(ull v) {
    float lo, hi; asm("mov.b64 {%0, %1}, %2;" : "=f"(lo), "=f"(hi) : "l"(v));
    return make_float2(lo, hi);
}
__device__ __forceinline__ unsigned smem_u32(const void* p) {
    unsigned a;
    asm("{ .reg .u64 t; cvta.to.shared.u64 t, %1; cvt.u32.u64 %0, t; }" : "=r"(a) : "l"(p));
    return a;
}
__device__ __forceinline__ void cp_async16(unsigned saddr, const void* gaddr) {
    asm volatile("cp.async.cg.shared.global [%0], [%1], 16;" :: "r"(saddr), "l"(gaddr));
}
#define CP_COMMIT() asm volatile("cp.async.commit_group;" ::: "memory")
#define CP_WAIT0()  asm volatile("cp.async.wait_group 0;" ::: "memory")

// ---------- K1: split W (x256) into fp16 hi/lo; reset flag counter ----------
__global__ void prep_kernel(const float* __restrict__ W) {
    if (blockIdx.x == 0 && threadIdx.x == 0) g_nflag = 0;
    const int total = NEXP * HDIM;
    for (int i = blockIdx.x * blockDim.x + threadIdx.x; i < total;
         i += gridDim.x * blockDim.x) {
        float ws = W[i] * 256.0f;
        __half h = __float2half_rn(ws);
        g_Whi[i] = h;
        g_Wlo[i] = __float2half_rn(ws - __half2float(h));
    }
}

// ---------- K2: wmma fp16 split-2 GEMM + bias + sigmoid (512 threads) ----------
__global__ __launch_bounds__(NTHR, 1)
void gemm_kernel(const float* __restrict__ X, const float* __restrict__ bvec, int T)
{
    extern __shared__ __half sh[];
    const int tid = threadIdx.x;
    const int wid = tid >> 5;
    const int n0 = blockIdx.x * BN;
    const int m0 = blockIdx.y * BM;
    const int wm = wid & 3;
    const int wn = wid >> 2;
    const unsigned sbase = smem_u32(sh);

    wmma::fragment<wmma::accumulator, 16, 16, 16, float> acc[2][2];
#pragma unroll
    for (int mt = 0; mt < 2; ++mt)
#pragma unroll
        for (int nt = 0; nt < 2; ++nt) wmma::fill_fragment(acc[mt][nt], 0.0f);

    float4 av[4];

    auto avload = [&](int it) {
        const int kc = it * BK;
#pragma unroll
        for (int i = 0; i < 4; ++i) {
            const int idx = tid + NTHR * i;
            const int row = idx >> 4, c4 = idx & 15;
            av[i] = __ldg((const float4*)(X + (size_t)(m0 + row) * HDIM + kc + c4 * 4));
        }
    };
    auto fillA = [&](int stage) {
        __half* Ahi = sh + stage * (STAGE_B / 2);
        __half* Alo = Ahi + MAT_B / 2;
#pragma unroll
        for (int i = 0; i < 4; ++i) {
            const int idx = tid + NTHR * i;
            const int row = idx >> 4, c4 = idx & 15;
            float4 v = av[i];
            __half2 h01 = __floats2half2_rn(v.x, v.y);
            __half2 h23 = __floats2half2_rn(v.z, v.w);
            float2 f01 = __half22float2(h01), f23 = __half22float2(h23);
            __half2 l01 = __floats2half2_rn(v.x - f01.x, v.y - f01.y);
            __half2 l23 = __floats2half2_rn(v.z - f23.x, v.w - f23.y);
            uint2 ph, pl;
            ph.x = reinterpret_cast<unsigned&>(h01); ph.y = reinterpret_cast<unsigned&>(h23);
            pl.x = reinterpret_cast<unsigned&>(l01); pl.y = reinterpret_cast<unsigned&>(l23);
            *(uint2*)(Ahi + row * LDH + c4 * 4) = ph;
            *(uint2*)(Alo + row * LDH + c4 * 4) = pl;
        }
    };
    auto cpB = [&](int it, int stage) {
        const int kc = it * BK;
        const unsigned bhi = sbase + stage * STAGE_B + 2 * MAT_B;
        const unsigned blo = bhi + MAT_B;
#pragma unroll
        for (int i = 0; i < 2; ++i) {
            const int idx = tid + NTHR * i;
            const int row = idx >> 3, c8 = idx & 7;
            const unsigned soff = (row * LDH + c8 * 8) * 2;
            const size_t goff = (size_t)(n0 + row) * HDIM + kc + c8 * 8;
            cp_async16(bhi + soff, g_Whi + goff);
            cp_async16(blo + soff, g_Wlo + goff);
        }
        CP_COMMIT();
    };

    cpB(0, 0);
    avload(0);
    fillA(0);
    avload(1);
    CP_WAIT0();
    __syncthreads();

    for (int it = 0; it < NIT; ++it) {
        const int buf = it & 1;
        if (it + 1 < NIT) cpB(it + 1, buf ^ 1);

        const __half* Ahi = sh + buf * (STAGE_B / 2);
        const __half* Alo = Ahi + MAT_B / 2;
        const __half* Bhi = Alo + MAT_B / 2;
        const __half* Blo = Bhi + MAT_B / 2;
#pragma unroll
        for (int kk = 0; kk < 4; ++kk) {
            wmma::fragment<wmma::matrix_a, 16, 16, 16, __half, wmma::row_major> ah[2], al[2];
#pragma unroll
            for (int mt = 0; mt < 2; ++mt) {
                const int r = wm * 32 + mt * 16;
                wmma::load_matrix_sync(ah[mt], Ahi + r * LDH + kk * 16, LDH);
                wmma::load_matrix_sync(al[mt], Alo + r * LDH + kk * 16, LDH);
            }
#pragma unroll
            for (int nt = 0; nt < 2; ++nt) {
                const int c = wn * 32 + nt * 16;
                wmma::fragment<wmma::matrix_b, 16, 16, 16, __half, wmma::col_major> fbh, fbl;
                wmma::load_matrix_sync(fbh, Bhi + c * LDH + kk * 16, LDH);
                wmma::load_matrix_sync(fbl, Blo + c * LDH + kk * 16, LDH);
#pragma unroll
                for (int mt = 0; mt < 2; ++mt) {
                    wmma::mma_sync(acc[mt][nt], ah[mt], fbh, acc[mt][nt]);
                    wmma::mma_sync(acc[mt][nt], ah[mt], fbl, acc[mt][nt]);
                    wmma::mma_sync(acc[mt][nt], al[mt], fbh, acc[mt][nt]);
                }
            }
        }
        if (it + 1 < NIT) {
            fillA(buf ^ 1);
            if (it + 2 < NIT) avload(it + 2);
            CP_WAIT0();
        }
        __syncthreads();
    }

    float* sacc = (float*)sh;
#pragma unroll
    for (int mt = 0; mt < 2; ++mt)
#pragma unroll
        for (int nt = 0; nt < 2; ++nt)
            wmma::store_matrix_sync(sacc + (wm * 32 + mt * 16) * 128 + wn * 32 + nt * 16,
                                    acc[mt][nt], 128, wmma::mem_row_major);
    __syncthreads();
#pragma unroll
    for (int i = 0; i < 8; ++i) {
        const int idx = tid + NTHR * i;
        const int row = idx >> 5, c4 = idx & 31;
        float4 v = *(float4*)(sacc + row * 128 + c4 * 4);
        const int n = n0 + c4 * 4;
        float4 o;
        o.x = 1.0f / (1.0f + expf(-(v.x * (1.0f/256.0f) + bvec[n])));
        o.y = 1.0f / (1.0f + expf(-(v.y * (1.0f/256.0f) + bvec[n+1])));
        o.z = 1.0f / (1.0f + expf(-(v.z * (1.0f/256.0f) + bvec[n+2])));
        o.w = 1.0f / (1.0f + expf(-(v.w * (1.0f/256.0f) + bvec[n+3])));
        *(float4*)(g_scores + (size_t)(m0 + row) * NEXP + n) = o;
    }
}

// ---------- warp-collective routing core ----------
__device__ __forceinline__ void route_token(const float* __restrict__ rs,
                                            const float* __restrict__ ebias,
                                            int lane, int t, int T,
                                            float* __restrict__ out, bool check)
{
    const float NEG_INF = -1e30f;
    float sfc[8];
#pragma unroll
    for (int i = 0; i < 8; ++i) sfc[i] = rs[i * 32 + lane] + ebias[i * 32 + lane];

    float gs[8];
#pragma unroll
    for (int i = 0; i < 8; ++i) {
        float m1 = sfc[i], m2 = NEG_INF;
#pragma unroll
        for (int off = 16; off > 0; off >>= 1) {
            float o1 = __shfl_xor_sync(0xffffffffu, m1, off);
            float o2 = __shfl_xor_sync(0xffffffffu, m2, off);
            float hi = fmaxf(m1, o1), lo = fminf(m1, o1);
            m1 = hi; m2 = fmaxf(fmaxf(m2, o2), lo);
        }
        gs[i] = m1 + m2;
    }

    unsigned gmask = 0, sel = 0;
    float g4 = 0.0f, g5 = 0.0f;
#pragma unroll
    for (int j = 0; j < 5; ++j) {
        float best = NEG_INF; int bg = 0;
#pragma unroll
        for (int g = 0; g < 8; ++g)
            if (!((sel >> g) & 1u) && gs[g] > best) { best = gs[g]; bg = g; }
        sel |= (1u << bg);
        if (j < 4) gmask |= (1u << bg);
        if (j == 3) g4 = best;
        if (j == 4) g5 = best;
    }

    float cv[8];
#pragma unroll
    for (int i = 0; i < 8; ++i) cv[i] = ((gmask >> i) & 1u) ? sfc[i] : 0.0f;

    unsigned used = 0;
    int idxs[8];
    float mmin = 1e30f, pv = 0.0f;
#pragma unroll
    for (int j = 0; j < 9; ++j) {
        float bv = NEG_INF; int be = 1 << 30;
#pragma unroll
        for (int i = 0; i < 8; ++i) {
            if (!((used >> i) & 1u)) {
                const float v = cv[i];
                const int e = i * 32 + lane;
                if (v > bv || (v == bv && e < be)) { bv = v; be = e; }
            }
        }
#pragma unroll
        for (int off = 16; off > 0; off >>= 1) {
            float ov = __shfl_xor_sync(0xffffffffu, bv, off);
            int oe = __shfl_xor_sync(0xffffffffu, be, off);
            if (ov > bv || (ov == bv && oe < be)) { bv = ov; be = oe; }
        }
        if (j < 8) idxs[j] = be;
        if ((be & 31) == lane) used |= (1u << (be >> 5));
        if (j > 0) mmin = fminf(mmin, pv - bv);
        pv = bv;
    }

    if (check && (mmin < TAU_E || (g4 - g5) < TAU_G)) {
        if (lane == 0) {
            int s = atomicAdd(&g_nflag, 1);
            if (s < RCAP) g_flags[s] = t;
        }
    }

    float wj = 0.0f;
    if (lane < TOPK) wj = rs[idxs[lane]];
    float ssum = wj;
#pragma unroll
    for (int off = 4; off > 0; off >>= 1)
        ssum += __shfl_xor_sync(0xffffffffu, ssum, off);
    const float denom = ssum + 1e-20f;
    if (lane < TOPK) {
        out[(size_t)t * TOPK + lane] = (float)idxs[lane];
        out[(size_t)T * TOPK + (size_t)t * TOPK + lane] = wj / denom * SCALE_F;
    }
}

// ---------- K3: router ----------
__global__ __launch_bounds__(128)
void router_kernel(const float* __restrict__ ebias, float* __restrict__ out, int T)
{
    __shared__ float raw_s[4][NEXP];
    const int warp = threadIdx.x >> 5;
    const int lane = threadIdx.x & 31;
    const int t = blockIdx.x * 4 + warp;
    if (t >= T) return;
    float* rs = raw_s[warp];
#pragma unroll
    for (int i = 0; i < 2; ++i)
        *(float4*)(rs + i * 128 + lane * 4) =
            *(const float4*)(g_scores + (size_t)t * NEXP + i * 128 + lane * 4);
    __syncwarp();
    route_token(rs, ebias, lane, t, T, out, true);
}

// ---------- K4: repair split-K mini-GEMM, tile-stride grid ----------
__global__ __launch_bounds__(256, 2)
void repair_gemm_kernel(const float* __restrict__ X, const float* __restrict__ W)
{
    const int nf = min(g_nflag, RCAP);
    const int ks = blockIdx.x;

    extern __shared__ float rsm[];
    float* xs = rsm;                     // [RTM][RKLEN] = 16 KB
    float* ws = rsm + RTM * RKLEN;       // [2][256][RWS_STRIDE]
    __shared__ int toks[RTM];

    const int tid = threadIdx.x;
    const ull neg1 = pack2(-1.0f, -1.0f);
    const int k0 = ks * RKLEN;

    for (int tile = blockIdx.y; tile * RTM < nf; tile += RTILES) {
        if (tid < RTM) toks[tid] = g_flags[min(tile * RTM + tid, nf - 1)];
        __syncthreads();

        // stage x slices
#pragma unroll
        for (int q = 0; q < 4; ++q) {
            const int f4 = tid + 256 * q;
            const int j = f4 >> 6, pos = f4 & 63;
            *(float4*)(xs + j * RKLEN + pos * 4) =
                __ldg((const float4*)(X + (size_t)toks[j] * HDIM + k0 + pos * 4));
        }

        float4 wreg[8];
        auto wload = [&](int c) {
            const int kc = k0 + c * 32;
#pragma unroll
            for (int q = 0; q < 8; ++q) {
                const int f4 = tid + 256 * q;
                const int row = f4 >> 3, c4 = f4 & 7;
                wreg[q] = __ldg((const float4*)(W + (size_t)row * HDIM + kc + c4 * 4));
            }
        };
        auto wstore = [&](int buf) {
            float* wb = ws + buf * RWS_BUF;
#pragma unroll
            for (int q = 0; q < 8; ++q) {
                const int f4 = tid + 256 * q;
                const int row = f4 >> 3, c4 = f4 & 7;
                float* p = wb + row * RWS_STRIDE + c4 * 4;
                p[0] = wreg[q].x; p[1] = wreg[q].y; p[2] = wreg[q].z; p[3] = wreg[q].w;
            }
        };

        ull run[RTM], acc[RTM], cmp[RTM];
#pragma unroll
        for (int j = 0; j < RTM; ++j) { run[j] = 0; acc[j] = 0; cmp[j] = 0; }

        wload(0);
        wstore(0);
        __syncthreads();
        wload(1);

        for (int c = 0; c < RNCH; ++c) {
            const int buf = c & 1;
            const float* wrow = ws + buf * RWS_BUF + tid * RWS_STRIDE;
            const float* xb = xs + c * 32;
#pragma unroll
            for (int u = 0; u < 16; ++u) {
                ull wv = *(const ull*)(wrow + 2 * u);
#pragma unroll
                for (int j = 0; j < RTM; ++j)
                    fma2_acc(run[j], wv, *(const ull*)(xb + j * RKLEN + 2 * u));
            }
#pragma unroll
            for (int j = 0; j < RTM; ++j) {
                ull y = fma2(cmp[j], neg1, run[j]);
                ull t2 = add2(acc[j], y);
                ull d = fma2(acc[j], neg1, t2);
                cmp[j] = fma2(y, neg1, d);
                acc[j] = t2;
                run[j] = 0;
            }
            if (c + 1 < RNCH) {
                wstore(buf ^ 1);
                if (c + 2 < RNCH) wload(c + 2);
            }
            __syncthreads();
        }

#pragma unroll
        for (int j = 0; j < RTM; ++j) {
            const int slot = tile * RTM + j;
            if (slot >= nf) break;
            float2 a = unpk2(acc[j]);
            float2 cc = unpk2(cmp[j]);
            float s = a.x + a.y;
            float bp = s - a.x;
            float r = (a.x - (s - bp)) + (a.y - bp);
            float e = r - (cc.x + cc.y);
            g_rep[ks][slot][tid] = make_float2(s, e);
        }
        __syncthreads();
    }
}

// ---------- K5: combine partials exactly, re-route flagged tokens ----------
__global__ __launch_bounds__(256)
void combine_kernel(const float* __restrict__ bvec, const float* __restrict__ ebias,
                    float* __restrict__ out, int T)
{
    __shared__ float sc[8][NEXP];
    const int warp = threadIdx.x >> 5;
    const int lane = threadIdx.x & 31;
    const int nf = min(g_nflag, RCAP);

    for (int slot = blockIdx.x * 8 + warp; slot < nf; slot += gridDim.x * 8) {
        const int t = g_flags[slot];
#pragma unroll
        for (int i = 0; i < 8; ++i) {
            const int e = i * 32 + lane;
            float s = 0.0f, err = 0.0f;
#pragma unroll
            for (int k = 0; k < RKS; ++k) {
                float2 p = g_rep[k][slot][e];
                float t2 = s + p.x;
                float bp = t2 - s;
                float r = (s - (t2 - bp)) + (p.x - bp);
                s = t2;
                err += r + p.y;
            }
            float l = s + (err + bvec[e]);
            sc[warp][e] = 1.0f / (1.0f + expf(-l));
        }
        __syncwarp();
        route_token(sc[warp], ebias, lane, t, T, out, false);
        __syncwarp();
    }
}

extern "C" void kernel_launch(void* const* d_in, const int* in_sizes, int n_in,
                              void* d_out, int out_size)
{
    const float* hs = (const float*)d_in[0];
    const float* W  = (const float*)d_in[1];
    const float* b  = (const float*)d_in[2];
    const float* eb = (const float*)d_in[3];
    const int T = in_sizes[0] / HDIM;

    cudaFuncSetAttribute(gemm_kernel, cudaFuncAttributeMaxDynamicSharedMemorySize, GEMM_SMEM);
    cudaFuncSetAttribute(repair_gemm_kernel, cudaFuncAttributeMaxDynamicSharedMemorySize, REP_SMEM);

    prep_kernel<<<256, 256>>>(W);
    dim3 ggrid(NEXP / BN, T / BM);
    gemm_kernel<<<ggrid, NTHR, GEMM_SMEM>>>(hs, b, T);
    router_kernel<<<(T + 3) / 4, 128>>>(eb, (float*)d_out, T);
    dim3 rgrid(RKS, RTILES);
    repair_gemm_kernel<<<rgrid, 256, REP_SMEM>>>(hs, W);
    combine_kernel<<<64, 256>>>(b, eb, (float*)d_out, T);
}